// round 4
// baseline (speedup 1.0000x reference)
#include <cuda_runtime.h>
#include <math.h>

// Problem shape (fixed by setup_inputs): B=32, grid=48, N=2304, D=1152, K=3
#define BB    32
#define NN    2304
#define DD    1152
#define KP    3
#define CELLS 256        // (48/3)^2
#define MAXC  16         // capacity per cell list (actual = 9)
#define D4    (DD/4)     // 288 float4 per row

// Global scratch (no allocation allowed in kernel_launch).
__device__ int g_count[BB * CELLS];
__device__ int g_list [BB * CELLS * MAXC];

// ---------------------------------------------------------------------------
// Kernel A: per-batch segment index build (deterministic, no atomics).
// One block per batch, 256 threads (= one thread per output cell).
// Self-detects whether position_ids arrived as int32 or int64.
// ---------------------------------------------------------------------------
__global__ void build_lists(const int* __restrict__ posw,
                            float* __restrict__ mask_f,          // may be null
                            unsigned char* __restrict__ mask_b,  // may be null
                            int mask_f_elems, int mask_b_elems)
{
    const int b = blockIdx.x;
    const int t = threadIdx.x;           // 0..255

    __shared__ int seg_sh[NN];
    __shared__ int red[256];
    __shared__ int mode32_sh;

    // --- dtype detection (batch 0 words; positions identical across batch) ---
    // int64 non-negative values: every odd 32-bit word == 0.
    // int32 layout: odd words are y-coords, nonzero from token 48 onward
    // (word 97 = y of token 48 = 1).
    if (t == 0) {
        int nz = 0;
        #pragma unroll 8
        for (int w = 1; w < 512; w += 2) nz |= posw[w];
        mode32_sh = (nz != 0) ? 1 : 0;
    }
    __syncthreads();
    const int is32 = mode32_sh;
    const long long* __restrict__ posl = (const long long*)posw;

    // --- max over n of max(pos_x, 0) ---
    int m = 0;
    for (int n = t; n < NN; n += 256) {
        int x;
        if (is32) {
            x = posw[((size_t)b * NN + n) * 2];
        } else {
            long long xl = posl[((size_t)b * NN + n) * 2];
            x = (xl > 0) ? (int)xl : 0;
        }
        if (x < 0) x = 0;
        m = max(m, x);
    }
    red[t] = m;
    __syncthreads();
    for (int s = 128; s > 0; s >>= 1) {
        if (t < s) red[t] = max(red[t], red[t + s]);
        __syncthreads();
    }
    const int stride = (red[0] + 1) / KP;   // max_x // K

    // --- seg per token into shared ---
    for (int n = t; n < NN; n += 256) {
        int x, y;
        if (is32) {
            x = posw[((size_t)b * NN + n) * 2];
            y = posw[((size_t)b * NN + n) * 2 + 1];
        } else {
            long long xl = posl[((size_t)b * NN + n) * 2];
            long long yl = posl[((size_t)b * NN + n) * 2 + 1];
            x = (xl > 0) ? (int)xl : 0;
            y = (yl > 0) ? (int)yl : 0;
        }
        if (x < 0) x = 0;
        if (y < 0) y = 0;
        seg_sh[n] = (x / KP) + stride * (y / KP);
    }
    __syncthreads();

    // --- each thread = one cell, scan all tokens in ascending order ---
    const int cell = t;
    const int base = (b * CELLS + cell) * MAXC;
    int cnt = 0;
    #pragma unroll 4
    for (int j = 0; j < NN; j++) {
        if (seg_sh[j] == cell) {
            if (cnt < MAXC) g_list[base + cnt] = j;
            cnt++;
        }
    }
    g_count[b * CELLS + cell] = min(cnt, MAXC);

    const int midx = b * CELLS + cell;
    const int valid = (cnt > 0) ? 1 : 0;
    if (mask_f && midx < mask_f_elems) mask_f[midx] = (float)valid;
    if (mask_b && midx < mask_b_elems) mask_b[midx] = (unsigned char)valid;
}

// ---------------------------------------------------------------------------
// Kernel B: gather-average. One block per (batch, cell), 288 threads,
// each thread owns one float4 column chunk. Fully coalesced; reads every
// hidden element exactly once.
// ---------------------------------------------------------------------------
__global__ __launch_bounds__(288)
void pool_gather(const float* __restrict__ hs,
                 const unsigned char* __restrict__ pad,
                 float* __restrict__ out,
                 float scale)
{
    const int blk = blockIdx.x;          // b*256 + cell
    const int b   = blk >> 8;
    const int t   = threadIdx.x;         // 0..287

    __shared__ int   idxs[MAXC];
    __shared__ float pmul[MAXC];
    __shared__ int   cnt_s;

    if (t == 0) cnt_s = g_count[blk];
    if (t < MAXC) {
        int n = g_list[blk * MAXC + t];
        if (n < 0 || n >= NN) n = 0;     // guard uninitialized slots
        idxs[t] = n;
        pmul[t] = pad[(size_t)b * NN + n] ? 0.0f : 1.0f;
    }
    __syncthreads();

    const int cnt = cnt_s;
    const float4* __restrict__ base =
        (const float4*)hs + (size_t)b * NN * D4;

    float ax = 0.f, ay = 0.f, az = 0.f, aw = 0.f;
    #pragma unroll 4
    for (int i = 0; i < cnt; i++) {
        const int   n = idxs[i];
        const float p = pmul[i];
        float4 v = base[(size_t)n * D4 + t];
        ax = fmaf(v.x, p, ax);
        ay = fmaf(v.y, p, ay);
        az = fmaf(v.z, p, az);
        aw = fmaf(v.w, p, aw);
    }

    float4 o;
    o.x = ax * scale; o.y = ay * scale; o.z = az * scale; o.w = aw * scale;
    ((float4*)out)[(size_t)blk * D4 + t] = o;
}

// ---------------------------------------------------------------------------
extern "C" void kernel_launch(void* const* d_in, const int* in_sizes, int n_in,
                              void* d_out, int out_size)
{
    const float*         hs   = (const float*)d_in[0];
    const int*           posw = (const int*)d_in[1];
    const unsigned char* pad  = (const unsigned char*)d_in[2];
    float* out = (float*)d_out;

    const int pooled_elems = BB * CELLS * DD;     // 9,437,184
    int extra = out_size - pooled_elems;          // tail beyond pooled, in floats

    float* mask_f = 0; unsigned char* mask_b = 0;
    int mf = 0, mb = 0;
    if (extra >= BB * CELLS) {                    // mask stored as float32
        mask_f = out + pooled_elems;
        mf = BB * CELLS;
    } else if (extra * 4 >= BB * CELLS) {         // mask stored as bool bytes
        mask_b = (unsigned char*)(out + pooled_elems);
        mb = BB * CELLS;
    }

    const float scale = sqrtf((float)DD) / (float)(KP * KP);

    build_lists<<<BB, 256>>>(posw, mask_f, mask_b, mf, mb);
    pool_gather<<<BB * CELLS, 288>>>(hs, pad, out, scale);
}

// round 5
// speedup vs baseline: 1.4072x; 1.4072x over previous
#include <cuda_runtime.h>
#include <math.h>

// Problem shape (fixed by setup_inputs): B=32, grid=48, N=2304, D=1152, K=3
#define BB    32
#define NN    2304
#define DD    1152
#define KP    3
#define CELLS 256        // (48/3)^2
#define MAXC  16         // capacity per cell list (actual = 9)
#define D4    (DD/4)     // 288 float4 per row

// Global scratch (no allocation allowed in kernel_launch).
__device__ int g_count[BB * CELLS];
__device__ int g_list [BB * CELLS * MAXC];
__device__ int g_mode;          // 1 = int32 position words, 0 = int64
__device__ int g_maxx[BB];      // per-batch max(max(pos_x,0))

// ---------------------------------------------------------------------------
// Kernel 0: per-batch max_x + position dtype detection. One block per batch.
// ---------------------------------------------------------------------------
__global__ void batch_info(const int* __restrict__ posw)
{
    __shared__ int red[256];
    __shared__ int mode_sh;
    const int b = blockIdx.x;
    const int t = threadIdx.x;

    // dtype detection: int64 non-negative values have every odd 32-bit
    // word == 0; int32 layout has nonzero y-words from token 48 onward.
    if (t == 0) {
        int nz = 0;
        #pragma unroll 8
        for (int w = 1; w < 512; w += 2) nz |= posw[w];
        mode_sh = (nz != 0) ? 1 : 0;
    }
    __syncthreads();
    const int is32 = mode_sh;
    const long long* __restrict__ posl = (const long long*)posw;

    int m = 0;
    for (int n = t; n < NN; n += 256) {
        int x;
        if (is32) {
            x = posw[((size_t)b * NN + n) * 2];
        } else {
            long long xl = posl[((size_t)b * NN + n) * 2];
            x = (xl > 0) ? (int)xl : 0;
        }
        if (x < 0) x = 0;
        m = max(m, x);
    }
    red[t] = m;
    __syncthreads();
    for (int s = 128; s > 0; s >>= 1) {
        if (t < s) red[t] = max(red[t], red[t + s]);
        __syncthreads();
    }
    if (t == 0) {
        g_maxx[b] = red[0];
        if (b == 0) g_mode = is32;
    }
}

// ---------------------------------------------------------------------------
// Kernel 1: list build, one WARP per (batch, cell). 1024 blocks x 8 warps.
// Lane l tests token n = i*32 + l; ballot + popc rank keeps exact
// ascending-n ordering per cell (deterministic, matches segment_sum order).
// ---------------------------------------------------------------------------
__global__ __launch_bounds__(256)
void build_lists(const int* __restrict__ posw,
                 float* __restrict__ mask_f,          // may be null
                 unsigned char* __restrict__ mask_b,  // may be null
                 int mask_f_elems, int mask_b_elems)
{
    const int bx   = blockIdx.x;          // 0 .. BB*32-1
    const int b    = bx >> 5;
    const int warp = threadIdx.x >> 5;
    const int lane = threadIdx.x & 31;
    const int cell = ((bx & 31) << 3) | warp;   // 0..255

    const int is32   = g_mode;
    const int stride = (g_maxx[b] + 1) / KP;
    const long long* __restrict__ posl = (const long long*)posw;
    const int base = (b * CELLS + cell) * MAXC;

    int cnt = 0;
    #pragma unroll 4
    for (int i = 0; i < NN / 32; i++) {
        const int n = i * 32 + lane;
        int x, y;
        if (is32) {
            int2 p = ((const int2*)posw)[(size_t)b * NN + n];
            x = p.x; y = p.y;
        } else {
            longlong2 p = ((const longlong2*)posl)[(size_t)b * NN + n];
            x = (p.x > 0) ? (int)p.x : 0;
            y = (p.y > 0) ? (int)p.y : 0;
        }
        if (x < 0) x = 0;
        if (y < 0) y = 0;
        const int seg = (x / KP) + stride * (y / KP);

        const unsigned mt = __ballot_sync(0xffffffffu, seg == cell);
        if (seg == cell) {
            const int rank = __popc(mt & ((1u << lane) - 1u));
            const int slot = cnt + rank;
            if (slot < MAXC) g_list[base + slot] = n;
        }
        cnt += __popc(mt);
    }

    if (lane == 0) {
        g_count[b * CELLS + cell] = min(cnt, MAXC);
        const int midx  = b * CELLS + cell;
        const int valid = (cnt > 0) ? 1 : 0;
        if (mask_f && midx < mask_f_elems) mask_f[midx] = (float)valid;
        if (mask_b && midx < mask_b_elems) mask_b[midx] = (unsigned char)valid;
    }
}

// ---------------------------------------------------------------------------
// Kernel 2: gather-average. One block per (batch, cell), 288 threads,
// each thread owns one float4 column chunk. Fully coalesced; reads every
// hidden element exactly once. cnt==9 fast path for full unroll / MLP.
// ---------------------------------------------------------------------------
__global__ __launch_bounds__(288)
void pool_gather(const float* __restrict__ hs,
                 const unsigned char* __restrict__ pad,
                 float* __restrict__ out,
                 float scale)
{
    const int blk = blockIdx.x;          // b*256 + cell
    const int b   = blk >> 8;
    const int t   = threadIdx.x;         // 0..287

    __shared__ int   idxs[MAXC];
    __shared__ float pmul[MAXC];
    __shared__ int   cnt_s;

    if (t == 0) cnt_s = g_count[blk];
    if (t < MAXC) {
        int n = g_list[blk * MAXC + t];
        if (n < 0 || n >= NN) n = 0;     // guard uninitialized slots
        idxs[t] = n;
        pmul[t] = pad[(size_t)b * NN + n] ? 0.0f : 1.0f;
    }
    __syncthreads();

    const int cnt = cnt_s;
    const float4* __restrict__ base =
        (const float4*)hs + (size_t)b * NN * D4;

    float ax = 0.f, ay = 0.f, az = 0.f, aw = 0.f;

    if (cnt == 9) {
        // Fast path: fully unrolled, 9 independent front-batched loads.
        float4 v[9];
        #pragma unroll
        for (int i = 0; i < 9; i++)
            v[i] = base[(size_t)idxs[i] * D4 + t];
        #pragma unroll
        for (int i = 0; i < 9; i++) {
            const float p = pmul[i];
            ax = fmaf(v[i].x, p, ax);
            ay = fmaf(v[i].y, p, ay);
            az = fmaf(v[i].z, p, az);
            aw = fmaf(v[i].w, p, aw);
        }
    } else {
        #pragma unroll 4
        for (int i = 0; i < cnt; i++) {
            const int   n = idxs[i];
            const float p = pmul[i];
            float4 v = base[(size_t)n * D4 + t];
            ax = fmaf(v.x, p, ax);
            ay = fmaf(v.y, p, ay);
            az = fmaf(v.z, p, az);
            aw = fmaf(v.w, p, aw);
        }
    }

    float4 o;
    o.x = ax * scale; o.y = ay * scale; o.z = az * scale; o.w = aw * scale;
    ((float4*)out)[(size_t)blk * D4 + t] = o;
}

// ---------------------------------------------------------------------------
extern "C" void kernel_launch(void* const* d_in, const int* in_sizes, int n_in,
                              void* d_out, int out_size)
{
    const float*         hs   = (const float*)d_in[0];
    const int*           posw = (const int*)d_in[1];
    const unsigned char* pad  = (const unsigned char*)d_in[2];
    float* out = (float*)d_out;

    const int pooled_elems = BB * CELLS * DD;     // 9,437,184
    int extra = out_size - pooled_elems;          // tail beyond pooled, in floats

    float* mask_f = 0; unsigned char* mask_b = 0;
    int mf = 0, mb = 0;
    if (extra >= BB * CELLS) {                    // mask stored as float32
        mask_f = out + pooled_elems;
        mf = BB * CELLS;
    } else if (extra * 4 >= BB * CELLS) {         // mask stored as bool bytes
        mask_b = (unsigned char*)(out + pooled_elems);
        mb = BB * CELLS;
    }

    const float scale = sqrtf((float)DD) / (float)(KP * KP);

    batch_info <<<BB, 256>>>(posw);
    build_lists<<<BB * 32, 256>>>(posw, mask_f, mask_b, mf, mb);
    pool_gather<<<BB * CELLS, 288>>>(hs, pad, out, scale);
}

// round 6
// speedup vs baseline: 1.8390x; 1.3069x over previous
#include <cuda_runtime.h>
#include <math.h>

// Problem shape (fixed by setup_inputs): B=32, grid=48, N=2304, D=1152, K=3
#define BB    32
#define NN    2304
#define DD    1152
#define KP    3
#define CELLS 256        // (48/3)^2
#define MAXC  16         // capacity per cell list (actual = 9)
#define D4    (DD/4)     // 288 float4 per row

// Global scratch (no allocation allowed in kernel_launch).
__device__ int g_count[BB * CELLS];
__device__ int g_list [BB * CELLS * MAXC];

// ---------------------------------------------------------------------------
// Kernel 1 (fused): per-batch dtype detect + max_x reduce + atomic scatter
// list build. One block per batch, 256 threads, ~9 tokens per thread.
// Shared-memory atomics assign slots; within-cell order is arbitrary, which
// only permutes the 9-term float sum (well inside the 1e-3 threshold).
// ---------------------------------------------------------------------------
__global__ __launch_bounds__(256)
void build_lists(const int* __restrict__ posw,
                 float* __restrict__ mask_f,          // may be null
                 unsigned char* __restrict__ mask_b,  // may be null
                 int mask_f_elems, int mask_b_elems)
{
    const int b = blockIdx.x;
    const int t = threadIdx.x;

    __shared__ int red[256];
    __shared__ int cnt_sh[CELLS];

    // --- dtype detection, fully parallel ---
    // int64 non-negative values: every odd 32-bit word of the buffer is 0.
    // int32 layout: odd words are y-coords, nonzero from token 48 on
    // (word 97 = y of token 48 = 1). Check first 128 odd words in parallel.
    const int is32 = __syncthreads_or((t < 128) && (posw[2 * t + 1] != 0));
    const long long* __restrict__ posl = (const long long*)posw;

    // --- pass 1: max over n of max(pos_x, 0) ---
    int m = 0;
    for (int n = t; n < NN; n += 256) {
        int x;
        if (is32) {
            x = posw[((size_t)b * NN + n) * 2];
        } else {
            long long xl = posl[((size_t)b * NN + n) * 2];
            x = (xl > 0) ? (int)xl : 0;
        }
        if (x < 0) x = 0;
        m = max(m, x);
    }
    red[t] = m;
    cnt_sh[t] = 0;                        // zero slot counters (CELLS == 256)
    __syncthreads();
    for (int s = 128; s > 0; s >>= 1) {
        if (t < s) red[t] = max(red[t], red[t + s]);
        __syncthreads();
    }
    const int stride = (red[0] + 1) / KP;   // max_x // K

    // --- pass 2: seg + atomic scatter into per-cell lists (positions L1-hot) ---
    for (int n = t; n < NN; n += 256) {
        int x, y;
        if (is32) {
            int2 p = ((const int2*)posw)[(size_t)b * NN + n];
            x = p.x; y = p.y;
        } else {
            longlong2 p = ((const longlong2*)posl)[(size_t)b * NN + n];
            x = (p.x > 0) ? (int)p.x : 0;
            y = (p.y > 0) ? (int)p.y : 0;
        }
        if (x < 0) x = 0;
        if (y < 0) y = 0;
        int seg = (x / KP) + stride * (y / KP);
        if (seg < 0) seg = 0;
        if (seg >= CELLS) seg = CELLS - 1;
        const int slot = atomicAdd(&cnt_sh[seg], 1);
        if (slot < MAXC)
            g_list[((size_t)(b * CELLS + seg)) * MAXC + slot] = n;
    }
    __syncthreads();

    // --- write counts + validity mask (thread t owns cell t) ---
    const int cnt = cnt_sh[t];
    g_count[b * CELLS + t] = min(cnt, MAXC);
    const int midx  = b * CELLS + t;
    const int valid = (cnt > 0) ? 1 : 0;
    if (mask_f && midx < mask_f_elems) mask_f[midx] = (float)valid;
    if (mask_b && midx < mask_b_elems) mask_b[midx] = (unsigned char)valid;
}

// ---------------------------------------------------------------------------
// Kernel 2: gather-average (proven R4 body: regs=32, occ 87%, 74% DRAM).
// One block per (batch, cell), 288 threads, one float4 column chunk each.
// Fully coalesced; reads every hidden element exactly once.
// ---------------------------------------------------------------------------
__global__ __launch_bounds__(288)
void pool_gather(const float* __restrict__ hs,
                 const unsigned char* __restrict__ pad,
                 float* __restrict__ out,
                 float scale)
{
    const int blk = blockIdx.x;          // b*256 + cell
    const int b   = blk >> 8;
    const int t   = threadIdx.x;         // 0..287

    __shared__ int   idxs[MAXC];
    __shared__ float pmul[MAXC];
    __shared__ int   cnt_s;

    if (t == 0) cnt_s = g_count[blk];
    if (t < MAXC) {
        int n = g_list[blk * MAXC + t];
        if (n < 0 || n >= NN) n = 0;     // guard uninitialized slots
        idxs[t] = n;
        pmul[t] = pad[(size_t)b * NN + n] ? 0.0f : 1.0f;
    }
    __syncthreads();

    const int cnt = cnt_s;
    const float4* __restrict__ base =
        (const float4*)hs + (size_t)b * NN * D4;

    float ax = 0.f, ay = 0.f, az = 0.f, aw = 0.f;
    #pragma unroll 4
    for (int i = 0; i < cnt; i++) {
        const int   n = idxs[i];
        const float p = pmul[i];
        float4 v = base[(size_t)n * D4 + t];
        ax = fmaf(v.x, p, ax);
        ay = fmaf(v.y, p, ay);
        az = fmaf(v.z, p, az);
        aw = fmaf(v.w, p, aw);
    }

    float4 o;
    o.x = ax * scale; o.y = ay * scale; o.z = az * scale; o.w = aw * scale;
    ((float4*)out)[(size_t)blk * D4 + t] = o;
}

// ---------------------------------------------------------------------------
extern "C" void kernel_launch(void* const* d_in, const int* in_sizes, int n_in,
                              void* d_out, int out_size)
{
    const float*         hs   = (const float*)d_in[0];
    const int*           posw = (const int*)d_in[1];
    const unsigned char* pad  = (const unsigned char*)d_in[2];
    float* out = (float*)d_out;

    const int pooled_elems = BB * CELLS * DD;     // 9,437,184
    int extra = out_size - pooled_elems;          // tail beyond pooled, in floats

    float* mask_f = 0; unsigned char* mask_b = 0;
    int mf = 0, mb = 0;
    if (extra >= BB * CELLS) {                    // mask stored as float32
        mask_f = out + pooled_elems;
        mf = BB * CELLS;
    } else if (extra * 4 >= BB * CELLS) {         // mask stored as bool bytes
        mask_b = (unsigned char*)(out + pooled_elems);
        mb = BB * CELLS;
    }

    const float scale = sqrtf((float)DD) / (float)(KP * KP);

    build_lists<<<BB, 256>>>(posw, mask_f, mask_b, mf, mb);
    pool_gather<<<BB * CELLS, 288>>>(hs, pad, out, scale);
}

// round 7
// speedup vs baseline: 1.8919x; 1.0287x over previous
#include <cuda_runtime.h>
#include <math.h>

// Problem shape (fixed by setup_inputs): B=32, grid=48, N=2304, D=1152, K=3
#define BB    32
#define NN    2304
#define DD    1152
#define KP    3
#define CELLS 256        // (48/3)^2
#define MAXC  16         // capacity per cell list (actual = 9)
#define D4    (DD/4)     // 288 float4 per row
#define TPB   288        // threads per block; NN/TPB == 8 exactly
#define TOKT  (NN/TPB)   // tokens scanned per thread

// ---------------------------------------------------------------------------
// Fused kernel: one block per (batch, cell). Each block
//   1) detects position dtype (int32 vs int64 words),
//   2) block-reduces max_x over its batch's positions (L2-resident, 18KB),
//   3) scans positions for tokens whose seg == this cell (shared atomic push),
//   4) gathers + averages the <=9 hidden rows, fully coalesced float4,
//   5) thread 0 writes the validity mask element.
// No inter-kernel dependency, single launch.
// ---------------------------------------------------------------------------
__global__ __launch_bounds__(TPB)
void pool_fused(const int*           __restrict__ posw,
                const float*         __restrict__ hs,
                const unsigned char* __restrict__ pad,
                float*               __restrict__ out,
                float*               __restrict__ mask_f,          // may be null
                unsigned char*       __restrict__ mask_b,          // may be null
                int mask_f_elems, int mask_b_elems,
                float scale)
{
    const int blk  = blockIdx.x;         // b*256 + cell
    const int b    = blk >> 8;
    const int cell = blk & 255;
    const int t    = threadIdx.x;        // 0..287
    const int warp = t >> 5;             // 0..8
    const int lane = t & 31;

    __shared__ int   idxs[MAXC];
    __shared__ float pmul[MAXC];
    __shared__ int   wmax[9];
    __shared__ int   cnt_sh;
    __shared__ int   mx_sh;

    if (t == 0) cnt_sh = 0;
    if (t < MAXC) idxs[t] = 0;           // default slot -> token 0 (guarded)

    // --- dtype detection (batch-0 words; parallel, folded into one barrier) ---
    // int64 non-negative values: every odd 32-bit word is 0.
    // int32 layout: odd words are y-coords, nonzero from token 48 onward.
    const int is32 = __syncthreads_or((t < 128) && (posw[2 * t + 1] != 0));
    const long long* __restrict__ posl = (const long long*)posw;

    // --- pass 1: block max of max(pos_x, 0) over this batch (8 tokens/thread) ---
    int m = 0;
    #pragma unroll
    for (int i = 0; i < TOKT; i++) {
        const int n = t + TPB * i;
        int x;
        if (is32) {
            x = posw[((size_t)b * NN + n) * 2];
        } else {
            long long xl = posl[((size_t)b * NN + n) * 2];
            x = (xl > 0) ? (int)xl : 0;
        }
        if (x < 0) x = 0;
        m = max(m, x);
    }
    #pragma unroll
    for (int s = 16; s > 0; s >>= 1)
        m = max(m, __shfl_xor_sync(0xffffffffu, m, s));
    if (lane == 0) wmax[warp] = m;
    __syncthreads();
    if (t == 0) {
        int mm = wmax[0];
        #pragma unroll
        for (int w = 1; w < 9; w++) mm = max(mm, wmax[w]);
        mx_sh = mm;
    }
    __syncthreads();
    const int stride = (mx_sh + 1) / KP;    // max_x // K

    // --- pass 2: scan for tokens in this cell (positions now L1/L2-hot) ---
    #pragma unroll
    for (int i = 0; i < TOKT; i++) {
        const int n = t + TPB * i;
        int x, y;
        if (is32) {
            int2 p = ((const int2*)posw)[(size_t)b * NN + n];
            x = p.x; y = p.y;
        } else {
            longlong2 p = ((const longlong2*)posl)[(size_t)b * NN + n];
            x = (p.x > 0) ? (int)p.x : 0;
            y = (p.y > 0) ? (int)p.y : 0;
        }
        if (x < 0) x = 0;
        if (y < 0) y = 0;
        const int seg = (x / KP) + stride * (y / KP);
        if (seg == cell) {
            const int slot = atomicAdd(&cnt_sh, 1);
            if (slot < MAXC) idxs[slot] = n;
        }
    }
    __syncthreads();

    const int rawcnt = cnt_sh;
    const int cnt    = min(rawcnt, MAXC);

    // --- padding multipliers for the selected tokens ---
    if (t < MAXC) {
        const int n = idxs[t];           // defaults to 0 beyond cnt (unused)
        pmul[t] = pad[(size_t)b * NN + n] ? 0.0f : 1.0f;
    }
    // --- validity mask ---
    if (t == 0) {
        const int valid = (rawcnt > 0) ? 1 : 0;
        if (mask_f && blk < mask_f_elems) mask_f[blk] = (float)valid;
        if (mask_b && blk < mask_b_elems) mask_b[blk] = (unsigned char)valid;
    }
    __syncthreads();

    // --- main gather (proven R4/R6 body: coalesced float4, unroll 4) ---
    const float4* __restrict__ base =
        (const float4*)hs + (size_t)b * NN * D4;

    float ax = 0.f, ay = 0.f, az = 0.f, aw = 0.f;
    #pragma unroll 4
    for (int i = 0; i < cnt; i++) {
        const int   n = idxs[i];
        const float p = pmul[i];
        float4 v = base[(size_t)n * D4 + t];
        ax = fmaf(v.x, p, ax);
        ay = fmaf(v.y, p, ay);
        az = fmaf(v.z, p, az);
        aw = fmaf(v.w, p, aw);
    }

    float4 o;
    o.x = ax * scale; o.y = ay * scale; o.z = az * scale; o.w = aw * scale;
    ((float4*)out)[(size_t)blk * D4 + t] = o;
}

// ---------------------------------------------------------------------------
extern "C" void kernel_launch(void* const* d_in, const int* in_sizes, int n_in,
                              void* d_out, int out_size)
{
    const float*         hs   = (const float*)d_in[0];
    const int*           posw = (const int*)d_in[1];
    const unsigned char* pad  = (const unsigned char*)d_in[2];
    float* out = (float*)d_out;

    const int pooled_elems = BB * CELLS * DD;     // 9,437,184
    int extra = out_size - pooled_elems;          // tail beyond pooled, in floats

    float* mask_f = 0; unsigned char* mask_b = 0;
    int mf = 0, mb = 0;
    if (extra >= BB * CELLS) {                    // mask stored as float32
        mask_f = out + pooled_elems;
        mf = BB * CELLS;
    } else if (extra * 4 >= BB * CELLS) {         // mask stored as bool bytes
        mask_b = (unsigned char*)(out + pooled_elems);
        mb = BB * CELLS;
    }

    const float scale = sqrtf((float)DD) / (float)(KP * KP);

    pool_fused<<<BB * CELLS, TPB>>>(posw, hs, pad, out,
                                    mask_f, mask_b, mf, mb, scale);
}

// round 8
// speedup vs baseline: 1.9488x; 1.0301x over previous
#include <cuda_runtime.h>
#include <math.h>

// Problem shape (fixed by setup_inputs): B=32, grid=48, N=2304, D=1152, K=3
#define BB    32
#define NN    2304
#define DD    1152
#define KP    3
#define CELLS 256        // (48/3)^2
#define MAXC  16         // capacity per cell list (actual = 9)
#define D4    (DD/4)     // 288 float4 per row
#define TPB   288        // threads per block; == D4
#define CPB   8          // cells per block
#define GRPS  (CELLS/CPB)// 32 cell-groups per batch

// ---------------------------------------------------------------------------
// Fused kernel: one block per (batch, group of 8 consecutive cells).
//   1) detect position dtype (int32 vs int64 words),
//   2) block-reduce max_x over this batch's positions (L2-resident),
//   3) scan positions once, collecting lists for all 8 cells in [c0, c0+8),
//   4) 8x the proven gather body: cell uniform per iteration, coalesced float4,
//   5) mask written for the 8 cells.
// Scan cost amortized 8x vs one-cell-per-block; 1024 blocks balance well.
// ---------------------------------------------------------------------------
__global__ __launch_bounds__(TPB)
void pool_fused(const int*           __restrict__ posw,
                const float*         __restrict__ hs,
                const unsigned char* __restrict__ pad,
                float*               __restrict__ out,
                float*               __restrict__ mask_f,          // may be null
                unsigned char*       __restrict__ mask_b,          // may be null
                int mask_f_elems, int mask_b_elems,
                float scale)
{
    const int blk  = blockIdx.x;          // b*GRPS + g
    const int b    = blk >> 5;            // GRPS == 32
    const int c0   = (blk & 31) * CPB;    // first cell of this block
    const int t    = threadIdx.x;         // 0..287
    const int warp = t >> 5;              // 0..8
    const int lane = t & 31;

    __shared__ int   idxs[CPB][MAXC];
    __shared__ float pmul[CPB][MAXC];
    __shared__ int   cnt_sh[CPB];
    __shared__ int   wmax[9];
    __shared__ int   mx_sh;

    if (t < CPB) cnt_sh[t] = 0;
    if (t < CPB * MAXC) idxs[t >> 4][t & 15] = 0;   // default -> token 0 (guarded)

    // --- dtype detection (parallel; folded into one barrier) ---
    // int64 non-negative: every odd 32-bit word is 0.
    // int32 layout: odd words are y-coords, nonzero from token 48 onward.
    const int is32 = __syncthreads_or((t < 128) && (posw[2 * t + 1] != 0));
    const long long* __restrict__ posl = (const long long*)posw;

    // --- pass 1: block max of max(pos_x, 0) ---
    int m = 0;
    for (int n = t; n < NN; n += TPB) {
        int x;
        if (is32) {
            x = posw[((size_t)b * NN + n) * 2];
        } else {
            long long xl = posl[((size_t)b * NN + n) * 2];
            x = (xl > 0) ? (int)xl : 0;
        }
        if (x < 0) x = 0;
        m = max(m, x);
    }
    #pragma unroll
    for (int s = 16; s > 0; s >>= 1)
        m = max(m, __shfl_xor_sync(0xffffffffu, m, s));
    if (lane == 0) wmax[warp] = m;
    __syncthreads();
    if (t == 0) {
        int mm = wmax[0];
        #pragma unroll
        for (int w = 1; w < 9; w++) mm = max(mm, wmax[w]);
        mx_sh = mm;
    }
    __syncthreads();
    const int stride = (mx_sh + 1) / KP;    // max_x // K

    // --- pass 2: one scan serving all 8 cells (positions L1/L2-hot) ---
    for (int n = t; n < NN; n += TPB) {
        int x, y;
        if (is32) {
            int2 p = ((const int2*)posw)[(size_t)b * NN + n];
            x = p.x; y = p.y;
        } else {
            longlong2 p = ((const longlong2*)posl)[(size_t)b * NN + n];
            x = (p.x > 0) ? (int)p.x : 0;
            y = (p.y > 0) ? (int)p.y : 0;
        }
        if (x < 0) x = 0;
        if (y < 0) y = 0;
        const int seg = (x / KP) + stride * (y / KP);
        const int rel = seg - c0;
        if ((unsigned)rel < CPB) {
            const int slot = atomicAdd(&cnt_sh[rel], 1);
            if (slot < MAXC) idxs[rel][slot] = n;
        }
    }
    __syncthreads();

    // --- padding multipliers (one thread per (cell, slot)) + mask ---
    if (t < CPB * MAXC) {
        const int n = idxs[t >> 4][t & 15];
        pmul[t >> 4][t & 15] = pad[(size_t)b * NN + n] ? 0.0f : 1.0f;
    }
    if (t < CPB) {
        const int midx  = b * CELLS + c0 + t;
        const int valid = (cnt_sh[t] > 0) ? 1 : 0;
        if (mask_f && midx < mask_f_elems) mask_f[midx] = (float)valid;
        if (mask_b && midx < mask_b_elems) mask_b[midx] = (unsigned char)valid;
    }
    __syncthreads();

    // --- main gather: 8x proven body; cell uniform across block per iter ---
    const float4* __restrict__ base =
        (const float4*)hs + (size_t)b * NN * D4;
    float4* __restrict__ obase =
        (float4*)out + ((size_t)(b * CELLS + c0)) * D4 + t;

    #pragma unroll
    for (int c = 0; c < CPB; c++) {
        const int cnt = min(cnt_sh[c], MAXC);
        float ax = 0.f, ay = 0.f, az = 0.f, aw = 0.f;
        #pragma unroll 4
        for (int i = 0; i < cnt; i++) {
            const int   n = idxs[c][i];
            const float p = pmul[c][i];
            float4 v = base[(size_t)n * D4 + t];
            ax = fmaf(v.x, p, ax);
            ay = fmaf(v.y, p, ay);
            az = fmaf(v.z, p, az);
            aw = fmaf(v.w, p, aw);
        }
        float4 o;
        o.x = ax * scale; o.y = ay * scale; o.z = az * scale; o.w = aw * scale;
        obase[(size_t)c * D4] = o;
    }
}

// ---------------------------------------------------------------------------
extern "C" void kernel_launch(void* const* d_in, const int* in_sizes, int n_in,
                              void* d_out, int out_size)
{
    const float*         hs   = (const float*)d_in[0];
    const int*           posw = (const int*)d_in[1];
    const unsigned char* pad  = (const unsigned char*)d_in[2];
    float* out = (float*)d_out;

    const int pooled_elems = BB * CELLS * DD;     // 9,437,184
    int extra = out_size - pooled_elems;          // tail beyond pooled, in floats

    float* mask_f = 0; unsigned char* mask_b = 0;
    int mf = 0, mb = 0;
    if (extra >= BB * CELLS) {                    // mask stored as float32
        mask_f = out + pooled_elems;
        mf = BB * CELLS;
    } else if (extra * 4 >= BB * CELLS) {         // mask stored as bool bytes
        mask_b = (unsigned char*)(out + pooled_elems);
        mb = BB * CELLS;
    }

    const float scale = sqrtf((float)DD) / (float)(KP * KP);

    pool_fused<<<BB * GRPS, TPB>>>(posw, hs, pad, out,
                                   mask_f, mask_b, mf, mb, scale);
}